// round 9
// baseline (speedup 1.0000x reference)
#include <cuda_runtime.h>
#include <cuda_bf16.h>
#include <math.h>

// Problem constants: x [16, 256, 128, 128] fp32, w [1, 2, 7, 7] fp32
// out [16, 1, 128, 128] fp32
#define B_  16
#define C_  256
#define H_  128
#define W_  128
#define HW_ (H_ * W_)          // 16384
#define HW4_ (HW_ / 4)         // 4096 float4 groups per plane
#define NCHUNK 4
#define CPC (C_ / NCHUNK)      // 64 channels per chunk
#define TH  8                  // output rows per conv tile
#define TR  (TH + 6)           // input rows per tile (halo +-3)
#define NITEMS (2 * TR * 32)   // 896 combine items per tile
#define CTHREADS 224           // combine threads: 896 / 224 = 4 items each

// Scratch: per-chunk partials [chunk][B][2][HW] (sum plane, max plane) = 8 MB
__device__ float g_part[NCHUNK * B_ * 2 * HW_];

// ---------------------------------------------------------------------------
// Kernel 1: partial channel sum + max over a 64-channel chunk.
// 1024 blocks = one balanced wave. __ldcs: streaming, evict-first.
// ---------------------------------------------------------------------------
__global__ __launch_bounds__(256) void reduce_partial_kernel(const float* __restrict__ x) {
    int chunk = blockIdx.x >> 8;                       // 0..3
    int t = ((blockIdx.x & 255) << 8) + threadIdx.x;   // 0..65535
    int b   = t >> 12;        // / 4096
    int sp4 = t & 4095;       // float4 group within plane

    const float4* base = reinterpret_cast<const float4*>(x)
                       + (size_t)b * C_ * HW4_ + (size_t)chunk * CPC * HW4_ + sp4;

    float4 sum = make_float4(0.f, 0.f, 0.f, 0.f);
    float4 mx  = make_float4(-INFINITY, -INFINITY, -INFINITY, -INFINITY);

    #pragma unroll 8
    for (int c = 0; c < CPC; ++c) {
        float4 v = __ldcs(base + c * HW4_);            // streaming, evict-first
        sum.x += v.x; sum.y += v.y; sum.z += v.z; sum.w += v.w;
        mx.x = fmaxf(mx.x, v.x); mx.y = fmaxf(mx.y, v.y);
        mx.z = fmaxf(mx.z, v.z); mx.w = fmaxf(mx.w, v.w);
    }

    float4* p_sum = reinterpret_cast<float4*>(g_part)
                  + (size_t)chunk * B_ * 2 * HW4_ + (size_t)b * 2 * HW4_ + sp4;
    float4* p_max = p_sum + HW4_;
    *p_sum = sum;
    *p_max = mx;
}

// ---------------------------------------------------------------------------
// Kernel 2 (fused): combine 4 chunk partials -> mean/max tile in smem, then
// 7x7 2-ch conv + sigmoid, 4-wide register blocked.
// Combine phase: threads 0..223 own exactly 4 items each, FULLY unrolled —
// all 32 LDG.128 issued before any smem store (max MLP; partials come from
// DRAM, need deep bytes-in-flight at low occupancy).
// ---------------------------------------------------------------------------
__global__ __launch_bounds__(256) void fused_combine_conv_kernel(const float* __restrict__ wgt,
                                                                 float* __restrict__ out) {
    __shared__ float4 sm[2][TR][32];   // [plane][input row][float4 group]  14 KB
    __shared__ float  ws[98];

    if (threadIdx.x < 98) ws[threadIdx.x] = __ldg(wgt + threadIdx.x);

    int b    = blockIdx.x >> 4;        // batch
    int tile = blockIdx.x & 15;        // 16 tiles of TH rows
    int h0   = tile * TH;              // first output row
    int r0   = h0 - 3;                 // first input row (may be < 0)

    const size_t cs = (size_t)B_ * 2 * HW4_;   // chunk stride in float4
    const float inv = 1.0f / (float)C_;
    const float4* pb = reinterpret_cast<const float4*>(g_part) + (size_t)b * 2 * HW4_;

    if (threadIdx.x < CTHREADS) {
        float4 regs[4][4];             // [item][chunk]
        int    pl[4], rr[4], gg[4];
        bool   valid[4];

        // Phase A: issue ALL loads (up to 32 LDG.128 in flight)
        #pragma unroll
        for (int k = 0; k < 4; ++k) {
            int i     = threadIdx.x + k * CTHREADS;      // 0..895
            int plane = i / (TR * 32);                   // boundary at 448
            int rem   = i - plane * (TR * 32);
            int r     = rem >> 5;
            int g     = rem & 31;
            int hh    = r0 + r;
            pl[k] = plane; rr[k] = r; gg[k] = g;
            valid[k] = ((unsigned)hh < (unsigned)H_);
            const float4* p = pb + (size_t)plane * HW4_ + (valid[k] ? hh : 0) * 32 + g;
            #pragma unroll
            for (int c = 0; c < 4; ++c)
                regs[k][c] = __ldg(p + c * cs);
        }

        // Phase B: reduce + store to smem
        #pragma unroll
        for (int k = 0; k < 4; ++k) {
            float4 v = make_float4(0.f, 0.f, 0.f, 0.f);
            if (valid[k]) {
                if (pl[k] == 0) {
                    v.x = (regs[k][0].x + regs[k][1].x + regs[k][2].x + regs[k][3].x) * inv;
                    v.y = (regs[k][0].y + regs[k][1].y + regs[k][2].y + regs[k][3].y) * inv;
                    v.z = (regs[k][0].z + regs[k][1].z + regs[k][2].z + regs[k][3].z) * inv;
                    v.w = (regs[k][0].w + regs[k][1].w + regs[k][2].w + regs[k][3].w) * inv;
                } else {
                    v.x = fmaxf(fmaxf(regs[k][0].x, regs[k][1].x), fmaxf(regs[k][2].x, regs[k][3].x));
                    v.y = fmaxf(fmaxf(regs[k][0].y, regs[k][1].y), fmaxf(regs[k][2].y, regs[k][3].y));
                    v.z = fmaxf(fmaxf(regs[k][0].z, regs[k][1].z), fmaxf(regs[k][2].z, regs[k][3].z));
                    v.w = fmaxf(fmaxf(regs[k][0].w, regs[k][1].w), fmaxf(regs[k][2].w, regs[k][3].w));
                }
            }
            sm[pl[k]][rr[k]][gg[k]] = v;
        }
    }
    __syncthreads();

    // Conv phase: thread -> (output row r, group g); 8 rows x 32 groups = 256
    int g = threadIdx.x & 31;
    int r = threadIdx.x >> 5;              // 0..7

    float acc0 = 0.f, acc1 = 0.f, acc2 = 0.f, acc3 = 0.f;
    const float4 z4 = make_float4(0.f, 0.f, 0.f, 0.f);

    #pragma unroll
    for (int ch = 0; ch < 2; ++ch) {
        const float* wp = ws + ch * 49;
        #pragma unroll
        for (int kh = 0; kh < 7; ++kh) {
            // input row index in smem = r + kh  (global row h0 + r - 3 + kh)
            float4 lo  = (g > 0)  ? sm[ch][r + kh][g - 1] : z4;
            float4 mid = sm[ch][r + kh][g];
            float4 hi  = (g < 31) ? sm[ch][r + kh][g + 1] : z4;
            float v[12] = { lo.x, lo.y, lo.z, lo.w,
                            mid.x, mid.y, mid.z, mid.w,
                            hi.x, hi.y, hi.z, hi.w };
            #pragma unroll
            for (int kw = 0; kw < 7; ++kw) {
                float wv = wp[kh * 7 + kw];
                acc0 = fmaf(v[kw + 1], wv, acc0);
                acc1 = fmaf(v[kw + 2], wv, acc1);
                acc2 = fmaf(v[kw + 3], wv, acc2);
                acc3 = fmaf(v[kw + 4], wv, acc3);
            }
        }
    }

    float4 res;
    res.x = 1.0f / (1.0f + __expf(-acc0));
    res.y = 1.0f / (1.0f + __expf(-acc1));
    res.z = 1.0f / (1.0f + __expf(-acc2));
    res.w = 1.0f / (1.0f + __expf(-acc3));
    reinterpret_cast<float4*>(out)[(size_t)b * HW4_ + (h0 + r) * 32 + g] = res;
}

extern "C" void kernel_launch(void* const* d_in, const int* in_sizes, int n_in,
                              void* d_out, int out_size) {
    const float* x = (const float*)d_in[0];
    const float* w = (const float*)d_in[1];
    float* out = (float*)d_out;

    reduce_partial_kernel<<<NCHUNK * 256, 256>>>(x);        // 1024 blocks
    fused_combine_conv_kernel<<<B_ * (H_ / TH), 256>>>(w, out);  // 256 blocks
}

// round 10
// speedup vs baseline: 1.0006x; 1.0006x over previous
#include <cuda_runtime.h>
#include <cuda_bf16.h>
#include <math.h>

// Problem constants: x [16, 256, 128, 128] fp32, w [1, 2, 7, 7] fp32
// out [16, 1, 128, 128] fp32
#define B_  16
#define C_  256
#define H_  128
#define W_  128
#define HW_ (H_ * W_)          // 16384
#define HW4_ (HW_ / 4)         // 4096 float4 groups per plane
#define NCHUNK 4
#define CPC (C_ / NCHUNK)      // 64 channels per chunk

// Fused-kernel tiling: 16 rows x 32 cols per block -> 512 blocks.
#define HT  16                 // output rows per tile
#define TRR (HT + 6)           // input rows incl. vertical halo = 22
#define GT  10                 // float4 groups incl. horizontal halo (8 + 2)
#define NIT (2 * TRR * GT)     // 440 combine items per block

// Scratch: per-chunk partials [chunk][B][2][HW] (sum plane, max plane) = 8 MB
__device__ float g_part[NCHUNK * B_ * 2 * HW_];

// ---------------------------------------------------------------------------
// Kernel 1: partial channel sum + max over a 64-channel chunk.
// 1024 blocks = one balanced wave. __ldcs: streaming, evict-first.
// ---------------------------------------------------------------------------
__global__ __launch_bounds__(256) void reduce_partial_kernel(const float* __restrict__ x) {
    int chunk = blockIdx.x >> 8;                       // 0..3
    int t = ((blockIdx.x & 255) << 8) + threadIdx.x;   // 0..65535
    int b   = t >> 12;        // / 4096
    int sp4 = t & 4095;       // float4 group within plane

    const float4* base = reinterpret_cast<const float4*>(x)
                       + (size_t)b * C_ * HW4_ + (size_t)chunk * CPC * HW4_ + sp4;

    float4 sum = make_float4(0.f, 0.f, 0.f, 0.f);
    float4 mx  = make_float4(-INFINITY, -INFINITY, -INFINITY, -INFINITY);

    #pragma unroll 8
    for (int c = 0; c < CPC; ++c) {
        float4 v = __ldcs(base + c * HW4_);            // streaming, evict-first
        sum.x += v.x; sum.y += v.y; sum.z += v.z; sum.w += v.w;
        mx.x = fmaxf(mx.x, v.x); mx.y = fmaxf(mx.y, v.y);
        mx.z = fmaxf(mx.z, v.z); mx.w = fmaxf(mx.w, v.w);
    }

    float4* p_sum = reinterpret_cast<float4*>(g_part)
                  + (size_t)chunk * B_ * 2 * HW4_ + (size_t)b * 2 * HW4_ + sp4;
    float4* p_max = p_sum + HW4_;
    *p_sum = sum;
    *p_max = mx;
}

// ---------------------------------------------------------------------------
// Kernel 2 (fused): combine 4 chunk partials -> mean/max tile in smem (with
// vertical AND horizontal halo, zero-padded), then 7x7 2-ch conv + sigmoid.
// 512 blocks x 256 threads. Each block: 16 rows x 32 cols of one batch.
// Combine: <=2 items/thread (8 LDG.128 batched). Conv: threads 0..127, 4
// horizontal pixels each; halo padding removes all boundary selects.
// ---------------------------------------------------------------------------
__global__ __launch_bounds__(256) void fused_combine_conv_kernel(const float* __restrict__ wgt,
                                                                 float* __restrict__ out) {
    __shared__ float4 sm[2][TRR][GT];  // 7 KB
    __shared__ float  ws[98];

    if (threadIdx.x < 98) ws[threadIdx.x] = __ldg(wgt + threadIdx.x);

    int bid = blockIdx.x;
    int b   = bid >> 5;                // batch
    int rem = bid & 31;
    int ht  = rem >> 2;                // 0..7  (h tile)
    int wt  = rem & 3;                 // 0..3  (w tile)
    int h0  = ht * HT;                 // first output row
    int w0g = wt * 8;                  // first output float4 group
    int gb  = w0g - 1;                 // first halo group (may be -1)

    const size_t cs = (size_t)B_ * 2 * HW4_;   // chunk stride in float4
    const float inv = 1.0f / (float)C_;
    const float4* pb = reinterpret_cast<const float4*>(g_part) + (size_t)b * 2 * HW4_;

    // ---- Combine phase: 440 items, threads own i = tid and tid+256 ----
    {
        float4 regs[2][4];
        int    pl[2], rr[2], jj[2];
        bool   valid[2];
        int    nit = (threadIdx.x + 256 < NIT) ? 2 : (threadIdx.x < NIT ? 1 : 0);

        #pragma unroll
        for (int k = 0; k < 2; ++k) {
            if (k < nit) {
                int i     = threadIdx.x + k * 256;
                int plane = i / (TRR * GT);            // boundary at 220
                int r2    = i - plane * (TRR * GT);
                int r     = r2 / GT;
                int j     = r2 - r * GT;
                int hh    = h0 - 3 + r;
                int gg    = gb + j;
                pl[k] = plane; rr[k] = r; jj[k] = j;
                valid[k] = ((unsigned)hh < (unsigned)H_) && ((unsigned)gg < 32u);
                const float4* p = pb + (size_t)plane * HW4_
                                + (valid[k] ? (hh * 32 + gg) : 0);
                #pragma unroll
                for (int c = 0; c < 4; ++c)
                    regs[k][c] = __ldg(p + c * cs);
            }
        }

        #pragma unroll
        for (int k = 0; k < 2; ++k) {
            if (k < nit) {
                float4 v = make_float4(0.f, 0.f, 0.f, 0.f);
                if (valid[k]) {
                    if (pl[k] == 0) {
                        v.x = (regs[k][0].x + regs[k][1].x + regs[k][2].x + regs[k][3].x) * inv;
                        v.y = (regs[k][0].y + regs[k][1].y + regs[k][2].y + regs[k][3].y) * inv;
                        v.z = (regs[k][0].z + regs[k][1].z + regs[k][2].z + regs[k][3].z) * inv;
                        v.w = (regs[k][0].w + regs[k][1].w + regs[k][2].w + regs[k][3].w) * inv;
                    } else {
                        v.x = fmaxf(fmaxf(regs[k][0].x, regs[k][1].x), fmaxf(regs[k][2].x, regs[k][3].x));
                        v.y = fmaxf(fmaxf(regs[k][0].y, regs[k][1].y), fmaxf(regs[k][2].y, regs[k][3].y));
                        v.z = fmaxf(fmaxf(regs[k][0].z, regs[k][1].z), fmaxf(regs[k][2].z, regs[k][3].z));
                        v.w = fmaxf(fmaxf(regs[k][0].w, regs[k][1].w), fmaxf(regs[k][2].w, regs[k][3].w));
                    }
                }
                sm[pl[k]][rr[k]][jj[k]] = v;
            }
        }
    }
    __syncthreads();

    // ---- Conv phase: threads 0..127 -> (row r, output group j), 4 pixels ----
    if (threadIdx.x < 128) {
        int r = threadIdx.x >> 3;          // 0..15
        int j = threadIdx.x & 7;           // 0..7

        float acc0 = 0.f, acc1 = 0.f, acc2 = 0.f, acc3 = 0.f;

        #pragma unroll
        for (int ch = 0; ch < 2; ++ch) {
            const float* wp = ws + ch * 49;
            #pragma unroll
            for (int kh = 0; kh < 7; ++kh) {
                float4 lo  = sm[ch][r + kh][j];        // halo group (zero-padded)
                float4 mid = sm[ch][r + kh][j + 1];
                float4 hi  = sm[ch][r + kh][j + 2];
                float v[12] = { lo.x, lo.y, lo.z, lo.w,
                                mid.x, mid.y, mid.z, mid.w,
                                hi.x, hi.y, hi.z, hi.w };
                #pragma unroll
                for (int kw = 0; kw < 7; ++kw) {
                    float wv = wp[kh * 7 + kw];
                    acc0 = fmaf(v[kw + 1], wv, acc0);
                    acc1 = fmaf(v[kw + 2], wv, acc1);
                    acc2 = fmaf(v[kw + 3], wv, acc2);
                    acc3 = fmaf(v[kw + 4], wv, acc3);
                }
            }
        }

        float4 res;
        res.x = 1.0f / (1.0f + __expf(-acc0));
        res.y = 1.0f / (1.0f + __expf(-acc1));
        res.z = 1.0f / (1.0f + __expf(-acc2));
        res.w = 1.0f / (1.0f + __expf(-acc3));
        reinterpret_cast<float4*>(out)[(size_t)b * HW4_ + (h0 + r) * 32 + w0g + j] = res;
    }
}

extern "C" void kernel_launch(void* const* d_in, const int* in_sizes, int n_in,
                              void* d_out, int out_size) {
    const float* x = (const float*)d_in[0];
    const float* w = (const float*)d_in[1];
    float* out = (float*)d_out;

    reduce_partial_kernel<<<NCHUNK * 256, 256>>>(x);       // 1024 blocks
    fused_combine_conv_kernel<<<512, 256>>>(w, out);       // 512 blocks
}